// round 15
// baseline (speedup 1.0000x reference)
#include <cuda_runtime.h>
#include <cuda_bf16.h>
#include <cuda_fp16.h>
#include <cstdint>

#define N_NODES 50000
#define N_EDGES 800000
#define IN_F    512
#define HD      256
#define NH      4

// ---------------- scratch (static __device__ — no allocation) ----------------
__device__ __half g_fth[N_NODES * HD];       // fp16 projected features
__device__ float g_el[N_NODES * NH];
__device__ float g_er[N_NODES * NH];
__device__ int   g_deg[N_NODES];
__device__ int   g_cursor[N_NODES];
__device__ int   g_row_start[N_NODES + 1];
__device__ int   g_incl[N_NODES];
__device__ int   g_blksum[64];
__device__ int   g_blkoff[64];
__device__ int   g_node_ctr;
__device__ int   g_csr_src[N_EDGES];
__device__ __nv_bfloat16 g_Whi[IN_F * HD];   // [K=512][N=256] row-major, hi part
__device__ __nv_bfloat16 g_Wlo[IN_F * HD];   // lo part

// ---------------- helpers ------------------------------------------------------
__device__ __forceinline__ uint32_t smem_u32(const void* p) {
    uint32_t a;
    asm("{ .reg .u64 t; cvta.to.shared.u64 t, %1; cvt.u32.u64 %0, t; }"
        : "=r"(a) : "l"(p));
    return a;
}

__device__ __forceinline__ void ldsm_x4(uint32_t* r, uint32_t addr) {
    asm volatile("ldmatrix.sync.aligned.m8n8.x4.shared.b16 {%0,%1,%2,%3}, [%4];"
                 : "=r"(r[0]), "=r"(r[1]), "=r"(r[2]), "=r"(r[3]) : "r"(addr));
}
__device__ __forceinline__ void ldsm_x4_t(uint32_t* r, uint32_t addr) {
    asm volatile("ldmatrix.sync.aligned.m8n8.x4.trans.shared.b16 {%0,%1,%2,%3}, [%4];"
                 : "=r"(r[0]), "=r"(r[1]), "=r"(r[2]), "=r"(r[3]) : "r"(addr));
}
__device__ __forceinline__ void mma16816(float* d, const uint32_t* a, const uint32_t* b) {
    asm volatile("mma.sync.aligned.m16n8k16.row.col.f32.bf16.bf16.f32 "
                 "{%0,%1,%2,%3}, {%4,%5,%6,%7}, {%8,%9}, {%0,%1,%2,%3};"
                 : "+f"(d[0]), "+f"(d[1]), "+f"(d[2]), "+f"(d[3])
                 : "r"(a[0]), "r"(a[1]), "r"(a[2]), "r"(a[3]), "r"(b[0]), "r"(b[1]));
}

__device__ __forceinline__ uint32_t pack_bf16x2(__nv_bfloat16 a, __nv_bfloat16 b) {
    __nv_bfloat162 p = __halves2bfloat162(a, b);
    return *reinterpret_cast<uint32_t*>(&p);
}

// 32B evict_last load = 16 halves per lane (v4.b64 shape, same as winning R13 path)
struct q4 { unsigned long long q[4]; };
__device__ __forceinline__ q4 ldg_fth16_evl(const __half* p) {
    q4 r;
    asm volatile("ld.global.nc.L2::evict_last.v4.b64 {%0,%1,%2,%3}, [%4];"
                 : "=l"(r.q[0]), "=l"(r.q[1]), "=l"(r.q[2]), "=l"(r.q[3]) : "l"(p));
    return r;
}
__device__ __forceinline__ void fma16h(float* acc, const q4& d, float w) {
#pragma unroll
    for (int j = 0; j < 4; j++) {
        uint32_t lo = (uint32_t)(d.q[j] & 0xffffffffu);
        uint32_t hi = (uint32_t)(d.q[j] >> 32);
        float2 f0 = __half22float2(*reinterpret_cast<__half2*>(&lo));
        float2 f1 = __half22float2(*reinterpret_cast<__half2*>(&hi));
        acc[j * 4 + 0] = fmaf(w, f0.x, acc[j * 4 + 0]);
        acc[j * 4 + 1] = fmaf(w, f0.y, acc[j * 4 + 1]);
        acc[j * 4 + 2] = fmaf(w, f1.x, acc[j * 4 + 2]);
        acc[j * 4 + 3] = fmaf(w, f1.y, acc[j * 4 + 3]);
    }
}
__device__ __forceinline__ void stg_cs(float* p, float4 v) {
    asm volatile("st.global.cs.v4.f32 [%0], {%1,%2,%3,%4};"
                 :: "l"(p), "f"(v.x), "f"(v.y), "f"(v.z), "f"(v.w) : "memory");
}

// ---------------- W split ------------------------------------------------------
__global__ void wsplit_kernel(const float* __restrict__ W) {
    int i = blockIdx.x * blockDim.x + threadIdx.x;
    if (i >= IN_F * HD) return;
    float w = W[i];
    __nv_bfloat16 hi = __float2bfloat16(w);
    float r = w - __bfloat162float(hi);
    g_Whi[i] = hi;
    g_Wlo[i] = __float2bfloat16(r);
}

__global__ void zero_kernel() {
    int i = blockIdx.x * blockDim.x + threadIdx.x;
    if (i < N_NODES) { g_deg[i] = 0; g_cursor[i] = 0; }
}

// ---------------- mma.sync GEMM: fth = feat @ W (fp16 out), fused el/er --------
#define A_STRIDE 40
#define B_STRIDE 264
#define A_BUF_B  (64 * A_STRIDE * 2)
#define B_BUF_B  (32 * B_STRIDE * 2)
#define OFF_AHI(b) ((b) * A_BUF_B)
#define OFF_ALO(b) (2 * A_BUF_B + (b) * A_BUF_B)
#define OFF_BHI(b) (4 * A_BUF_B + (b) * B_BUF_B)
#define OFF_BLO(b) (4 * A_BUF_B + 2 * B_BUF_B + (b) * B_BUF_B)
#define GEMM_SMEM  (4 * A_BUF_B + 4 * B_BUF_B)

__global__ __launch_bounds__(512, 1)
void mma_gemm_kernel(const float* __restrict__ feat,
                     const float* __restrict__ al,
                     const float* __restrict__ ar) {
    extern __shared__ char smem[];
    const uint32_t sb = smem_u32(smem);

    const int tid    = threadIdx.x;
    const int lane   = tid & 31;
    const int wid    = tid >> 5;
    const int warp_m = wid & 3;
    const int warp_n = wid >> 2;
    const int row_base = blockIdx.x * 64;

    const int a_r = tid >> 3;
    const int a_c = (tid & 7) * 4;
    const int a_g = row_base + a_r;
    const int b_r = tid >> 4;
    const int b_c = (tid & 15) * 16;

    const uint32_t aStoreOff = (uint32_t)(a_r * A_STRIDE + a_c) * 2u;
    const uint32_t bStoreOff = (uint32_t)(b_r * B_STRIDE + b_c) * 2u;

    float acc[8][4];
#pragma unroll
    for (int nf = 0; nf < 8; nf++)
#pragma unroll
        for (int j = 0; j < 4; j++) acc[nf][j] = 0.f;

    float4 a_pf;
    uint4  bh_pf[2], bl_pf[2];

    auto load_chunk = [&](int c) {
        int k0 = c * 32;
        a_pf = make_float4(0.f, 0.f, 0.f, 0.f);
        if (a_g < N_NODES)
            a_pf = *reinterpret_cast<const float4*>(feat + (long)a_g * IN_F + k0 + a_c);
        const uint4* ph = reinterpret_cast<const uint4*>(g_Whi + (k0 + b_r) * HD + b_c);
        const uint4* pl = reinterpret_cast<const uint4*>(g_Wlo + (k0 + b_r) * HD + b_c);
        bh_pf[0] = ph[0]; bh_pf[1] = ph[1];
        bl_pf[0] = pl[0]; bl_pf[1] = pl[1];
    };
    auto store_chunk = [&](int buf) {
        __nv_bfloat16 h0 = __float2bfloat16(a_pf.x);
        __nv_bfloat16 h1 = __float2bfloat16(a_pf.y);
        __nv_bfloat16 h2 = __float2bfloat16(a_pf.z);
        __nv_bfloat16 h3 = __float2bfloat16(a_pf.w);
        __nv_bfloat16 l0 = __float2bfloat16(a_pf.x - __bfloat162float(h0));
        __nv_bfloat16 l1 = __float2bfloat16(a_pf.y - __bfloat162float(h1));
        __nv_bfloat16 l2 = __float2bfloat16(a_pf.z - __bfloat162float(h2));
        __nv_bfloat16 l3 = __float2bfloat16(a_pf.w - __bfloat162float(h3));
        uint2 hh = make_uint2(pack_bf16x2(h0, h1), pack_bf16x2(h2, h3));
        uint2 ll = make_uint2(pack_bf16x2(l0, l1), pack_bf16x2(l2, l3));
        *reinterpret_cast<uint2*>(smem + OFF_AHI(buf) + aStoreOff) = hh;
        *reinterpret_cast<uint2*>(smem + OFF_ALO(buf) + aStoreOff) = ll;
        *reinterpret_cast<uint4*>(smem + OFF_BHI(buf) + bStoreOff)      = bh_pf[0];
        *reinterpret_cast<uint4*>(smem + OFF_BHI(buf) + bStoreOff + 16) = bh_pf[1];
        *reinterpret_cast<uint4*>(smem + OFF_BLO(buf) + bStoreOff)      = bl_pf[0];
        *reinterpret_cast<uint4*>(smem + OFF_BLO(buf) + bStoreOff + 16) = bl_pf[1];
    };

    const uint32_t aLdOffBase = (uint32_t)((warp_m * 16 + (lane & 15)) * A_STRIDE + (lane >> 4) * 8) * 2u;
    const uint32_t bLdRow     = (uint32_t)(lane & 15);
    const uint32_t bLdColBase = (uint32_t)(warp_n * 64 + (lane >> 4) * 8);

    load_chunk(0);
    store_chunk(0);
    load_chunk(1);

    for (int c = 0; c < 16; c++) {
        const int buf = c & 1;
        __syncthreads();
        if (c < 15) store_chunk(buf ^ 1);
        if (c < 14) load_chunk(c + 2);

        const uint32_t aHiB = sb + OFF_AHI(buf);
        const uint32_t aLoB = sb + OFF_ALO(buf);
        const uint32_t bHiB = sb + OFF_BHI(buf);
        const uint32_t bLoB = sb + OFF_BLO(buf);

#pragma unroll
        for (int ks = 0; ks < 32; ks += 16) {
            uint32_t ah[4], alr[4];
            {
                uint32_t off = aLdOffBase + (uint32_t)ks * 2u;
                ldsm_x4(ah,  aHiB + off);
                ldsm_x4(alr, aLoB + off);
            }
            uint32_t bh[4][4], bl[4][4];
#pragma unroll
            for (int np = 0; np < 4; np++) {
                uint32_t off = ((uint32_t)(ks + bLdRow) * B_STRIDE + bLdColBase + np * 16) * 2u;
                ldsm_x4_t(bh[np], bHiB + off);
                ldsm_x4_t(bl[np], bLoB + off);
            }
#pragma unroll
            for (int nf = 0; nf < 8; nf++) {
                const uint32_t* bph = &bh[nf >> 1][(nf & 1) * 2];
                const uint32_t* bpl = &bl[nf >> 1][(nf & 1) * 2];
                mma16816(acc[nf], ah,  bph);
                mma16816(acc[nf], ah,  bpl);
                mma16816(acc[nf], alr, bph);
            }
        }
    }

    const int head = warp_n;
    float alv[16], arv[16];
#pragma unroll
    for (int nf = 0; nf < 8; nf++) {
#pragma unroll
        for (int j = 0; j < 2; j++) {
            int col = nf * 8 + (lane & 3) * 2 + j;
            alv[nf * 2 + j] = al[head * 64 + col];
            arv[nf * 2 + j] = ar[head * 64 + col];
        }
    }

    int r0 = row_base + warp_m * 16 + (lane >> 2);
    int r1 = r0 + 8;
    float pl0 = 0.f, pr0 = 0.f, pl1 = 0.f, pr1 = 0.f;

#pragma unroll
    for (int nf = 0; nf < 8; nf++) {
        float c0 = acc[nf][0], c1 = acc[nf][1], c2 = acc[nf][2], c3 = acc[nf][3];
        int colg = head * 64 + nf * 8 + (lane & 3) * 2;
        if (r0 < N_NODES)
            *reinterpret_cast<__half2*>(g_fth + (long)r0 * HD + colg) = __floats2half2_rn(c0, c1);
        if (r1 < N_NODES)
            *reinterpret_cast<__half2*>(g_fth + (long)r1 * HD + colg) = __floats2half2_rn(c2, c3);
        pl0 = fmaf(c0, alv[nf * 2], fmaf(c1, alv[nf * 2 + 1], pl0));
        pr0 = fmaf(c0, arv[nf * 2], fmaf(c1, arv[nf * 2 + 1], pr0));
        pl1 = fmaf(c2, alv[nf * 2], fmaf(c3, alv[nf * 2 + 1], pl1));
        pr1 = fmaf(c2, arv[nf * 2], fmaf(c3, arv[nf * 2 + 1], pr1));
    }
#pragma unroll
    for (int off = 1; off < 4; off <<= 1) {
        pl0 += __shfl_xor_sync(0xffffffffu, pl0, off);
        pr0 += __shfl_xor_sync(0xffffffffu, pr0, off);
        pl1 += __shfl_xor_sync(0xffffffffu, pl1, off);
        pr1 += __shfl_xor_sync(0xffffffffu, pr1, off);
    }
    if ((lane & 3) == 0) {
        if (r0 < N_NODES) { g_el[r0 * NH + head] = pl0; g_er[r0 * NH + head] = pr0; }
        if (r1 < N_NODES) { g_el[r1 * NH + head] = pl1; g_er[r1 * NH + head] = pr1; }
    }
}

// ---------------- CSR build ---------------------------------------------------
__global__ void hist_kernel(const int* __restrict__ dst) {
    int i = blockIdx.x * blockDim.x + threadIdx.x;
    int base = i * 4;
    if (base + 3 < N_EDGES) {
        int4 d = *reinterpret_cast<const int4*>(dst + base);
        atomicAdd(&g_deg[d.x], 1);
        atomicAdd(&g_deg[d.y], 1);
        atomicAdd(&g_deg[d.z], 1);
        atomicAdd(&g_deg[d.w], 1);
    } else {
        for (int e = base; e < N_EDGES; e++) atomicAdd(&g_deg[dst[e]], 1);
    }
}

#define SCAN_BLOCKS ((N_NODES + 1023) / 1024)   // 49

__global__ __launch_bounds__(1024)
void scan1_kernel() {
    int i = blockIdx.x * 1024 + threadIdx.x;
    int lane = threadIdx.x & 31, wid = threadIdx.x >> 5;
    int v = (i < N_NODES) ? g_deg[i] : 0;
    int x = v;
#pragma unroll
    for (int off = 1; off < 32; off <<= 1) {
        int y = __shfl_up_sync(0xffffffffu, x, off);
        if (lane >= off) x += y;
    }
    __shared__ int ws[32];
    if (lane == 31) ws[wid] = x;
    __syncthreads();
    if (wid == 0) {
        int y = ws[lane];
#pragma unroll
        for (int off = 1; off < 32; off <<= 1) {
            int z = __shfl_up_sync(0xffffffffu, y, off);
            if (lane >= off) y += z;
        }
        ws[lane] = y;
    }
    __syncthreads();
    if (wid > 0) x += ws[wid - 1];
    if (i < N_NODES) g_incl[i] = x;
    if (threadIdx.x == 1023) g_blksum[blockIdx.x] = x;
}

__global__ void scan2_kernel() {
    int t = threadIdx.x;
    int lane = t & 31, wid = t >> 5;
    int v = (t < SCAN_BLOCKS) ? g_blksum[t] : 0;
    int x = v;
#pragma unroll
    for (int off = 1; off < 32; off <<= 1) {
        int y = __shfl_up_sync(0xffffffffu, x, off);
        if (lane >= off) x += y;
    }
    __shared__ int ws[2];
    if (lane == 31) ws[wid] = x;
    __syncthreads();
    if (wid == 1) x += ws[0];
    g_blkoff[t] = x - v;
    if (t == 63) g_row_start[N_NODES] = x;
    if (t == 0) g_node_ctr = 0;
}

__global__ __launch_bounds__(1024)
void scan3_kernel() {
    int i = blockIdx.x * 1024 + threadIdx.x;
    if (i < N_NODES)
        g_row_start[i] = g_incl[i] - g_deg[i] + g_blkoff[i >> 10];
}

__global__ void scatter_kernel(const int* __restrict__ src, const int* __restrict__ dst) {
    int i = blockIdx.x * blockDim.x + threadIdx.x;
    int base = i * 4;
    if (base + 3 < N_EDGES) {
        int4 d = *reinterpret_cast<const int4*>(dst + base);
        int4 s = *reinterpret_cast<const int4*>(src + base);
        g_csr_src[g_row_start[d.x] + atomicAdd(&g_cursor[d.x], 1)] = s.x;
        g_csr_src[g_row_start[d.y] + atomicAdd(&g_cursor[d.y], 1)] = s.y;
        g_csr_src[g_row_start[d.z] + atomicAdd(&g_cursor[d.z], 1)] = s.z;
        g_csr_src[g_row_start[d.w] + atomicAdd(&g_cursor[d.w], 1)] = s.w;
    } else {
        for (int e = base; e < N_EDGES; e++) {
            int v = dst[e];
            g_csr_src[g_row_start[v] + atomicAdd(&g_cursor[v], 1)] = src[e];
        }
    }
}

// ---------------- aggregation: pair-edge fp16 gather ----------------------------
// Lanes 0-15 cover edge e's 512B row (16 halves each); lanes 16-31 edge e+1.
#define MAX_DEG 128

__global__ __launch_bounds__(256)
void aggregate_kernel(float* __restrict__ out) {
    __shared__ float sw[8][MAX_DEG * NH];   // per-warp weight cache (16KB)
    const int lane = threadIdx.x & 31;
    const int hh   = lane & 3;
    const int slot = lane >> 2;
    const int half_idx = lane >> 4;          // 0: even edge, 1: odd edge
    const int fl   = lane & 15;              // feature lane: 16 halves each
    const int hd   = fl >> 2;                // head of this lane's features
    float* swp = sw[threadIdx.x >> 5];

    while (true) {
        int base;
        if (lane == 0) base = atomicAdd(&g_node_ctr, 2);
        base = __shfl_sync(0xffffffffu, base, 0);
        if (base >= N_NODES) break;
        int vend = (base + 2 < N_NODES) ? base + 2 : N_NODES;

        for (int v = base; v < vend; v++) {
            int start = g_row_start[v];
            int end   = g_row_start[v + 1];
            int d     = end - start;
            const bool small = d <= MAX_DEG;

            // ---- pass 1: online softmax stats; stash scores in smem if small.
            float er_h = g_er[v * NH + hh];
            float m = -1e30f, ssum = 0.f;
            for (int e = start + slot; e < end; e += 8) {
                int s = g_csr_src[e];
                float x = g_el[s * NH + hh] + er_h;
                x = (x > 0.f) ? x : 0.2f * x;
                if (small) swp[(e - start) * NH + hh] = x;
                float mn = fmaxf(m, x);
                ssum = ssum * __expf(m - mn) + __expf(x - mn);
                m = mn;
            }
#pragma unroll
            for (int off = 4; off < 32; off <<= 1) {
                float m2 = __shfl_xor_sync(0xffffffffu, m, off);
                float s2 = __shfl_xor_sync(0xffffffffu, ssum, off);
                float mn = fmaxf(m, m2);
                ssum = ssum * __expf(m - mn) + s2 * __expf(m2 - mn);
                m = mn;
            }
            float inv_h = (ssum > 0.f) ? (1.0f / ssum) : 0.f;

            if (small) {
                for (int e = start + slot; e < end; e += 8) {
                    int idx = (e - start) * NH + hh;
                    swp[idx] = __expf(swp[idx] - m) * inv_h;
                }
            }
            __syncwarp();

            float acc[16];
#pragma unroll
            for (int k = 0; k < 16; k++) acc[k] = 0.f;

            if (small) {
                int ep = 0;
                for (; ep + 3 < d; ep += 4) {   // 2 full pairs in flight
                    int eA = start + ep + half_idx;
                    int eB = eA + 2;
                    int sA = g_csr_src[eA];
                    int sB = g_csr_src[eB];
                    float wA = swp[(ep + half_idx) * NH + hd];
                    float wB = swp[(ep + 2 + half_idx) * NH + hd];
                    q4 a = ldg_fth16_evl(g_fth + (long)sA * HD + fl * 16);
                    q4 b = ldg_fth16_evl(g_fth + (long)sB * HD + fl * 16);
                    fma16h(acc, a, wA);
                    fma16h(acc, b, wB);
                }
                for (; ep < d; ep += 2) {       // tail pair (possibly half)
                    int ee = ep + half_idx;
                    bool valid = ee < d;
                    int e = start + (valid ? ee : 0);
                    int s = g_csr_src[e];
                    float w = valid ? swp[ee * NH + hd] : 0.f;
                    q4 u = ldg_fth16_evl(g_fth + (long)s * HD + fl * 16);
                    fma16h(acc, u, w);
                }
            } else {
                float m_g  = __shfl_sync(0xffffffffu, m, hd);
                float i_g  = __shfl_sync(0xffffffffu, inv_h, hd);
                float er_g = __shfl_sync(0xffffffffu, er_h, hd);
                for (int ep = 0; ep < d; ep += 2) {
                    int ee = ep + half_idx;
                    bool valid = ee < d;
                    int e = start + (valid ? ee : 0);
                    int s = g_csr_src[e];
                    float x = g_el[s * NH + hd] + er_g;
                    x = (x > 0.f) ? x : 0.2f * x;
                    float w = valid ? __expf(x - m_g) * i_g : 0.f;
                    q4 u = ldg_fth16_evl(g_fth + (long)s * HD + fl * 16);
                    fma16h(acc, u, w);
                }
            }

            // merge even/odd-edge partials: lane l <-> l+16 hold same features
#pragma unroll
            for (int k = 0; k < 16; k++)
                acc[k] += __shfl_xor_sync(0xffffffffu, acc[k], 16);

            // store: lane covers features fl*16 + half_idx*8 .. +8
            float* op = out + (long)v * HD + fl * 16 + half_idx * 8;
            int k0 = half_idx * 8;
            stg_cs(op,     make_float4(acc[k0], acc[k0 + 1], acc[k0 + 2], acc[k0 + 3]));
            stg_cs(op + 4, make_float4(acc[k0 + 4], acc[k0 + 5], acc[k0 + 6], acc[k0 + 7]));
            __syncwarp();
        }
    }
}

// ---------------- launch ------------------------------------------------------
extern "C" void kernel_launch(void* const* d_in, const int* in_sizes, int n_in,
                              void* d_out, int out_size) {
    const float* feat = (const float*)d_in[0];
    const float* W    = (const float*)d_in[1];
    const float* al   = (const float*)d_in[2];
    const float* ar   = (const float*)d_in[3];
    const int*   src  = (const int*)d_in[4];
    const int*   dst  = (const int*)d_in[5];
    float* out = (float*)d_out;

    static int inited = 0;
    static cudaStream_t s2;
    static cudaEvent_t ev_fork, ev_join;
    if (!inited) {
        cudaFuncSetAttribute(mma_gemm_kernel,
                             cudaFuncAttributeMaxDynamicSharedMemorySize, GEMM_SMEM);
        cudaStreamCreateWithFlags(&s2, cudaStreamNonBlocking);
        cudaEventCreateWithFlags(&ev_fork, cudaEventDisableTiming);
        cudaEventCreateWithFlags(&ev_join, cudaEventDisableTiming);
        inited = 1;
    }

    cudaEventRecord(ev_fork, 0);
    cudaStreamWaitEvent(s2, ev_fork, 0);

    // -- stream 0: projection path --
    wsplit_kernel<<<(IN_F * HD + 255) / 256, 256>>>(W);
    mma_gemm_kernel<<<(N_NODES + 63) / 64, 512, GEMM_SMEM>>>(feat, al, ar);

    // -- stream s2: CSR build path --
    zero_kernel<<<(N_NODES + 255) / 256, 256, 0, s2>>>();
    hist_kernel<<<(N_EDGES / 4 + 255) / 256, 256, 0, s2>>>(dst);
    scan1_kernel<<<SCAN_BLOCKS, 1024, 0, s2>>>();
    scan2_kernel<<<1, 64, 0, s2>>>();
    scan3_kernel<<<SCAN_BLOCKS, 1024, 0, s2>>>();
    scatter_kernel<<<(N_EDGES / 4 + 255) / 256, 256, 0, s2>>>(src, dst);

    cudaEventRecord(ev_join, s2);
    cudaStreamWaitEvent(0, ev_join, 0);

    aggregate_kernel<<<1184, 256>>>(out);
}

// round 16
// speedup vs baseline: 1.0425x; 1.0425x over previous
#include <cuda_runtime.h>
#include <cuda_bf16.h>
#include <cstdint>

#define N_NODES 50000
#define N_EDGES 800000
#define IN_F    512
#define HD      256
#define NH      4

// ---------------- scratch (static __device__ — no allocation) ----------------
__device__ float g_ft[N_NODES * HD];
__device__ float g_el[N_NODES * NH];
__device__ float g_er[N_NODES * NH];
__device__ int   g_deg[N_NODES];
__device__ int   g_cursor[N_NODES];
__device__ int   g_row_start[N_NODES + 1];
__device__ int   g_incl[N_NODES];
__device__ int   g_blksum[64];
__device__ int   g_blkoff[64];
__device__ int   g_node_ctr;
__device__ int   g_csr_src[N_EDGES];
__device__ __nv_bfloat16 g_Whi[IN_F * HD];   // [K=512][N=256] row-major, hi part
__device__ __nv_bfloat16 g_Wlo[IN_F * HD];   // lo part

// ---------------- helpers ------------------------------------------------------
__device__ __forceinline__ uint32_t smem_u32(const void* p) {
    uint32_t a;
    asm("{ .reg .u64 t; cvta.to.shared.u64 t, %1; cvt.u32.u64 %0, t; }"
        : "=r"(a) : "l"(p));
    return a;
}

__device__ __forceinline__ void ldsm_x4(uint32_t* r, uint32_t addr) {
    asm volatile("ldmatrix.sync.aligned.m8n8.x4.shared.b16 {%0,%1,%2,%3}, [%4];"
                 : "=r"(r[0]), "=r"(r[1]), "=r"(r[2]), "=r"(r[3]) : "r"(addr));
}
__device__ __forceinline__ void ldsm_x4_t(uint32_t* r, uint32_t addr) {
    asm volatile("ldmatrix.sync.aligned.m8n8.x4.trans.shared.b16 {%0,%1,%2,%3}, [%4];"
                 : "=r"(r[0]), "=r"(r[1]), "=r"(r[2]), "=r"(r[3]) : "r"(addr));
}
__device__ __forceinline__ void mma16816(float* d, const uint32_t* a, const uint32_t* b) {
    asm volatile("mma.sync.aligned.m16n8k16.row.col.f32.bf16.bf16.f32 "
                 "{%0,%1,%2,%3}, {%4,%5,%6,%7}, {%8,%9}, {%0,%1,%2,%3};"
                 : "+f"(d[0]), "+f"(d[1]), "+f"(d[2]), "+f"(d[3])
                 : "r"(a[0]), "r"(a[1]), "r"(a[2]), "r"(a[3]), "r"(b[0]), "r"(b[1]));
}

__device__ __forceinline__ uint32_t pack_bf16x2(__nv_bfloat16 a, __nv_bfloat16 b) {
    __nv_bfloat162 p = __halves2bfloat162(a, b);
    return *reinterpret_cast<uint32_t*>(&p);
}

// L2-policy memory ops (protected R13 path): 32B evict_last loads, .cs stores
struct f8 { float v[8]; };
__device__ __forceinline__ f8 ldg_ft_evl8(const float* p) {
    unsigned long long q0, q1, q2, q3;
    asm volatile("ld.global.nc.L2::evict_last.v4.b64 {%0,%1,%2,%3}, [%4];"
                 : "=l"(q0), "=l"(q1), "=l"(q2), "=l"(q3) : "l"(p));
    f8 r;
    asm("mov.b64 {%0, %1}, %2;" : "=f"(r.v[0]), "=f"(r.v[1]) : "l"(q0));
    asm("mov.b64 {%0, %1}, %2;" : "=f"(r.v[2]), "=f"(r.v[3]) : "l"(q1));
    asm("mov.b64 {%0, %1}, %2;" : "=f"(r.v[4]), "=f"(r.v[5]) : "l"(q2));
    asm("mov.b64 {%0, %1}, %2;" : "=f"(r.v[6]), "=f"(r.v[7]) : "l"(q3));
    return r;
}
__device__ __forceinline__ void stg_cs(float* p, float4 v) {
    asm volatile("st.global.cs.v4.f32 [%0], {%1,%2,%3,%4};"
                 :: "l"(p), "f"(v.x), "f"(v.y), "f"(v.z), "f"(v.w) : "memory");
}

// ---------------- W split ------------------------------------------------------
__global__ void wsplit_kernel(const float* __restrict__ W) {
    int i = blockIdx.x * blockDim.x + threadIdx.x;
    if (i >= IN_F * HD) return;
    float w = W[i];
    __nv_bfloat16 hi = __float2bfloat16(w);
    float r = w - __bfloat162float(hi);
    g_Whi[i] = hi;
    g_Wlo[i] = __float2bfloat16(r);
}

__global__ void zero_kernel() {
    int i = blockIdx.x * blockDim.x + threadIdx.x;
    if (i < N_NODES) { g_deg[i] = 0; g_cursor[i] = 0; }
}

// ---------------- mma.sync GEMM: g_ft = feat @ W, fused el/er ------------------
#define A_STRIDE 40
#define B_STRIDE 264
#define A_BUF_B  (64 * A_STRIDE * 2)
#define B_BUF_B  (32 * B_STRIDE * 2)
#define OFF_AHI(b) ((b) * A_BUF_B)
#define OFF_ALO(b) (2 * A_BUF_B + (b) * A_BUF_B)
#define OFF_BHI(b) (4 * A_BUF_B + (b) * B_BUF_B)
#define OFF_BLO(b) (4 * A_BUF_B + 2 * B_BUF_B + (b) * B_BUF_B)
#define GEMM_SMEM  (4 * A_BUF_B + 4 * B_BUF_B)

__global__ __launch_bounds__(512, 1)
void mma_gemm_kernel(const float* __restrict__ feat,
                     const float* __restrict__ al,
                     const float* __restrict__ ar) {
    extern __shared__ char smem[];
    const uint32_t sb = smem_u32(smem);

    const int tid    = threadIdx.x;
    const int lane   = tid & 31;
    const int wid    = tid >> 5;
    const int warp_m = wid & 3;
    const int warp_n = wid >> 2;
    const int row_base = blockIdx.x * 64;

    const int a_r = tid >> 3;
    const int a_c = (tid & 7) * 4;
    const int a_g = row_base + a_r;
    const int b_r = tid >> 4;
    const int b_c = (tid & 15) * 16;

    const uint32_t aStoreOff = (uint32_t)(a_r * A_STRIDE + a_c) * 2u;
    const uint32_t bStoreOff = (uint32_t)(b_r * B_STRIDE + b_c) * 2u;

    float acc[8][4];
#pragma unroll
    for (int nf = 0; nf < 8; nf++)
#pragma unroll
        for (int j = 0; j < 4; j++) acc[nf][j] = 0.f;

    float4 a_pf;
    uint4  bh_pf[2], bl_pf[2];

    auto load_chunk = [&](int c) {
        int k0 = c * 32;
        a_pf = make_float4(0.f, 0.f, 0.f, 0.f);
        if (a_g < N_NODES)
            a_pf = *reinterpret_cast<const float4*>(feat + (long)a_g * IN_F + k0 + a_c);
        const uint4* ph = reinterpret_cast<const uint4*>(g_Whi + (k0 + b_r) * HD + b_c);
        const uint4* pl = reinterpret_cast<const uint4*>(g_Wlo + (k0 + b_r) * HD + b_c);
        bh_pf[0] = ph[0]; bh_pf[1] = ph[1];
        bl_pf[0] = pl[0]; bl_pf[1] = pl[1];
    };
    auto store_chunk = [&](int buf) {
        __nv_bfloat16 h0 = __float2bfloat16(a_pf.x);
        __nv_bfloat16 h1 = __float2bfloat16(a_pf.y);
        __nv_bfloat16 h2 = __float2bfloat16(a_pf.z);
        __nv_bfloat16 h3 = __float2bfloat16(a_pf.w);
        __nv_bfloat16 l0 = __float2bfloat16(a_pf.x - __bfloat162float(h0));
        __nv_bfloat16 l1 = __float2bfloat16(a_pf.y - __bfloat162float(h1));
        __nv_bfloat16 l2 = __float2bfloat16(a_pf.z - __bfloat162float(h2));
        __nv_bfloat16 l3 = __float2bfloat16(a_pf.w - __bfloat162float(h3));
        uint2 hh = make_uint2(pack_bf16x2(h0, h1), pack_bf16x2(h2, h3));
        uint2 ll = make_uint2(pack_bf16x2(l0, l1), pack_bf16x2(l2, l3));
        *reinterpret_cast<uint2*>(smem + OFF_AHI(buf) + aStoreOff) = hh;
        *reinterpret_cast<uint2*>(smem + OFF_ALO(buf) + aStoreOff) = ll;
        *reinterpret_cast<uint4*>(smem + OFF_BHI(buf) + bStoreOff)      = bh_pf[0];
        *reinterpret_cast<uint4*>(smem + OFF_BHI(buf) + bStoreOff + 16) = bh_pf[1];
        *reinterpret_cast<uint4*>(smem + OFF_BLO(buf) + bStoreOff)      = bl_pf[0];
        *reinterpret_cast<uint4*>(smem + OFF_BLO(buf) + bStoreOff + 16) = bl_pf[1];
    };

    const uint32_t aLdOffBase = (uint32_t)((warp_m * 16 + (lane & 15)) * A_STRIDE + (lane >> 4) * 8) * 2u;
    const uint32_t bLdRow     = (uint32_t)(lane & 15);
    const uint32_t bLdColBase = (uint32_t)(warp_n * 64 + (lane >> 4) * 8);

    load_chunk(0);
    store_chunk(0);
    load_chunk(1);

    for (int c = 0; c < 16; c++) {
        const int buf = c & 1;
        __syncthreads();
        if (c < 15) store_chunk(buf ^ 1);
        if (c < 14) load_chunk(c + 2);

        const uint32_t aHiB = sb + OFF_AHI(buf);
        const uint32_t aLoB = sb + OFF_ALO(buf);
        const uint32_t bHiB = sb + OFF_BHI(buf);
        const uint32_t bLoB = sb + OFF_BLO(buf);

#pragma unroll
        for (int ks = 0; ks < 32; ks += 16) {
            uint32_t ah[4], alr[4];
            {
                uint32_t off = aLdOffBase + (uint32_t)ks * 2u;
                ldsm_x4(ah,  aHiB + off);
                ldsm_x4(alr, aLoB + off);
            }
            uint32_t bh[4][4], bl[4][4];
#pragma unroll
            for (int np = 0; np < 4; np++) {
                uint32_t off = ((uint32_t)(ks + bLdRow) * B_STRIDE + bLdColBase + np * 16) * 2u;
                ldsm_x4_t(bh[np], bHiB + off);
                ldsm_x4_t(bl[np], bLoB + off);
            }
#pragma unroll
            for (int nf = 0; nf < 8; nf++) {
                const uint32_t* bph = &bh[nf >> 1][(nf & 1) * 2];
                const uint32_t* bpl = &bl[nf >> 1][(nf & 1) * 2];
                mma16816(acc[nf], ah,  bph);
                mma16816(acc[nf], ah,  bpl);
                mma16816(acc[nf], alr, bph);
            }
        }
    }

    const int head = warp_n;
    float alv[16], arv[16];
#pragma unroll
    for (int nf = 0; nf < 8; nf++) {
#pragma unroll
        for (int j = 0; j < 2; j++) {
            int col = nf * 8 + (lane & 3) * 2 + j;
            alv[nf * 2 + j] = al[head * 64 + col];
            arv[nf * 2 + j] = ar[head * 64 + col];
        }
    }

    int r0 = row_base + warp_m * 16 + (lane >> 2);
    int r1 = r0 + 8;
    float pl0 = 0.f, pr0 = 0.f, pl1 = 0.f, pr1 = 0.f;

#pragma unroll
    for (int nf = 0; nf < 8; nf++) {
        float c0 = acc[nf][0], c1 = acc[nf][1], c2 = acc[nf][2], c3 = acc[nf][3];
        int colg = head * 64 + nf * 8 + (lane & 3) * 2;
        if (r0 < N_NODES)
            *reinterpret_cast<float2*>(g_ft + (long)r0 * HD + colg) = make_float2(c0, c1);
        if (r1 < N_NODES)
            *reinterpret_cast<float2*>(g_ft + (long)r1 * HD + colg) = make_float2(c2, c3);
        pl0 = fmaf(c0, alv[nf * 2], fmaf(c1, alv[nf * 2 + 1], pl0));
        pr0 = fmaf(c0, arv[nf * 2], fmaf(c1, arv[nf * 2 + 1], pr0));
        pl1 = fmaf(c2, alv[nf * 2], fmaf(c3, alv[nf * 2 + 1], pl1));
        pr1 = fmaf(c2, arv[nf * 2], fmaf(c3, arv[nf * 2 + 1], pr1));
    }
#pragma unroll
    for (int off = 1; off < 4; off <<= 1) {
        pl0 += __shfl_xor_sync(0xffffffffu, pl0, off);
        pr0 += __shfl_xor_sync(0xffffffffu, pr0, off);
        pl1 += __shfl_xor_sync(0xffffffffu, pl1, off);
        pr1 += __shfl_xor_sync(0xffffffffu, pr1, off);
    }
    if ((lane & 3) == 0) {
        if (r0 < N_NODES) { g_el[r0 * NH + head] = pl0; g_er[r0 * NH + head] = pr0; }
        if (r1 < N_NODES) { g_el[r1 * NH + head] = pl1; g_er[r1 * NH + head] = pr1; }
    }
}

// ---------------- CSR build ---------------------------------------------------
__global__ void hist_kernel(const int* __restrict__ dst) {
    int i = blockIdx.x * blockDim.x + threadIdx.x;
    int base = i * 4;
    if (base + 3 < N_EDGES) {
        int4 d = *reinterpret_cast<const int4*>(dst + base);
        atomicAdd(&g_deg[d.x], 1);
        atomicAdd(&g_deg[d.y], 1);
        atomicAdd(&g_deg[d.z], 1);
        atomicAdd(&g_deg[d.w], 1);
    } else {
        for (int e = base; e < N_EDGES; e++) atomicAdd(&g_deg[dst[e]], 1);
    }
}

#define SCAN_BLOCKS ((N_NODES + 1023) / 1024)   // 49

__global__ __launch_bounds__(1024)
void scan1_kernel() {
    int i = blockIdx.x * 1024 + threadIdx.x;
    int lane = threadIdx.x & 31, wid = threadIdx.x >> 5;
    int v = (i < N_NODES) ? g_deg[i] : 0;
    int x = v;
#pragma unroll
    for (int off = 1; off < 32; off <<= 1) {
        int y = __shfl_up_sync(0xffffffffu, x, off);
        if (lane >= off) x += y;
    }
    __shared__ int ws[32];
    if (lane == 31) ws[wid] = x;
    __syncthreads();
    if (wid == 0) {
        int y = ws[lane];
#pragma unroll
        for (int off = 1; off < 32; off <<= 1) {
            int z = __shfl_up_sync(0xffffffffu, y, off);
            if (lane >= off) y += z;
        }
        ws[lane] = y;
    }
    __syncthreads();
    if (wid > 0) x += ws[wid - 1];
    if (i < N_NODES) g_incl[i] = x;
    if (threadIdx.x == 1023) g_blksum[blockIdx.x] = x;
}

__global__ void scan2_kernel() {
    int t = threadIdx.x;
    int lane = t & 31, wid = t >> 5;
    int v = (t < SCAN_BLOCKS) ? g_blksum[t] : 0;
    int x = v;
#pragma unroll
    for (int off = 1; off < 32; off <<= 1) {
        int y = __shfl_up_sync(0xffffffffu, x, off);
        if (lane >= off) x += y;
    }
    __shared__ int ws[2];
    if (lane == 31) ws[wid] = x;
    __syncthreads();
    if (wid == 1) x += ws[0];
    g_blkoff[t] = x - v;
    if (t == 63) g_row_start[N_NODES] = x;
    if (t == 0) g_node_ctr = 0;
}

__global__ __launch_bounds__(1024)
void scan3_kernel() {
    int i = blockIdx.x * 1024 + threadIdx.x;
    if (i < N_NODES)
        g_row_start[i] = g_incl[i] - g_deg[i] + g_blkoff[i >> 10];
}

__global__ void scatter_kernel(const int* __restrict__ src, const int* __restrict__ dst) {
    int i = blockIdx.x * blockDim.x + threadIdx.x;
    int base = i * 4;
    if (base + 3 < N_EDGES) {
        int4 d = *reinterpret_cast<const int4*>(dst + base);
        int4 s = *reinterpret_cast<const int4*>(src + base);
        g_csr_src[g_row_start[d.x] + atomicAdd(&g_cursor[d.x], 1)] = s.x;
        g_csr_src[g_row_start[d.y] + atomicAdd(&g_cursor[d.y], 1)] = s.y;
        g_csr_src[g_row_start[d.z] + atomicAdd(&g_cursor[d.z], 1)] = s.z;
        g_csr_src[g_row_start[d.w] + atomicAdd(&g_cursor[d.w], 1)] = s.w;
    } else {
        for (int e = base; e < N_EDGES; e++) {
            int v = dst[e];
            g_csr_src[g_row_start[v] + atomicAdd(&g_cursor[v], 1)] = src[e];
        }
    }
}

// ---------------- aggregation: single fused pass, unnormalized accumulate ------
// Scores are O(10) so exp() never overflows fp32; divide by ssum at the end.
__global__ __launch_bounds__(256)
void aggregate_kernel(float* __restrict__ out) {
    const int lane = threadIdx.x & 31;
    const int hg   = lane >> 3;              // head for this lane's features

    while (true) {
        int base;
        if (lane == 0) base = atomicAdd(&g_node_ctr, 2);
        base = __shfl_sync(0xffffffffu, base, 0);
        if (base >= N_NODES) break;
        int vend = (base + 2 < N_NODES) ? base + 2 : N_NODES;

        for (int v = base; v < vend; v++) {
            int start = g_row_start[v];
            int end   = g_row_start[v + 1];
            float er_g = g_er[v * NH + hg];

            float ssum = 0.f;
            float acc[8];
#pragma unroll
            for (int k = 0; k < 8; k++) acc[k] = 0.f;

            int e = start;
            for (; e + 1 < end; e += 2) {
                int s0 = g_csr_src[e];
                int s1 = g_csr_src[e + 1];
                // issue both ft loads before the weight math
                f8 a = ldg_ft_evl8(g_ft + (long)s0 * HD + lane * 8);
                f8 b = ldg_ft_evl8(g_ft + (long)s1 * HD + lane * 8);
                float x0 = g_el[s0 * NH + hg] + er_g;
                float x1 = g_el[s1 * NH + hg] + er_g;
                x0 = (x0 > 0.f) ? x0 : 0.2f * x0;
                x1 = (x1 > 0.f) ? x1 : 0.2f * x1;
                float w0 = __expf(x0);
                float w1 = __expf(x1);
                ssum += w0 + w1;
#pragma unroll
                for (int k = 0; k < 8; k++) acc[k] = fmaf(w0, a.v[k], acc[k]);
#pragma unroll
                for (int k = 0; k < 8; k++) acc[k] = fmaf(w1, b.v[k], acc[k]);
            }
            if (e < end) {
                int s = g_csr_src[e];
                f8 u = ldg_ft_evl8(g_ft + (long)s * HD + lane * 8);
                float x = g_el[s * NH + hg] + er_g;
                x = (x > 0.f) ? x : 0.2f * x;
                float w = __expf(x);
                ssum += w;
#pragma unroll
                for (int k = 0; k < 8; k++) acc[k] = fmaf(w, u.v[k], acc[k]);
            }

            float inv = (ssum > 0.f) ? (1.0f / ssum) : 0.f;
            float* op = out + (long)v * HD + lane * 8;
            stg_cs(op,     make_float4(acc[0] * inv, acc[1] * inv, acc[2] * inv, acc[3] * inv));
            stg_cs(op + 4, make_float4(acc[4] * inv, acc[5] * inv, acc[6] * inv, acc[7] * inv));
        }
    }
}

// ---------------- launch ------------------------------------------------------
extern "C" void kernel_launch(void* const* d_in, const int* in_sizes, int n_in,
                              void* d_out, int out_size) {
    const float* feat = (const float*)d_in[0];
    const float* W    = (const float*)d_in[1];
    const float* al   = (const float*)d_in[2];
    const float* ar   = (const float*)d_in[3];
    const int*   src  = (const int*)d_in[4];
    const int*   dst  = (const int*)d_in[5];
    float* out = (float*)d_out;

    static int inited = 0;
    static cudaStream_t s2;
    static cudaEvent_t ev_fork, ev_join;
    if (!inited) {
        cudaFuncSetAttribute(mma_gemm_kernel,
                             cudaFuncAttributeMaxDynamicSharedMemorySize, GEMM_SMEM);
        cudaStreamCreateWithFlags(&s2, cudaStreamNonBlocking);
        cudaEventCreateWithFlags(&ev_fork, cudaEventDisableTiming);
        cudaEventCreateWithFlags(&ev_join, cudaEventDisableTiming);
        inited = 1;
    }

    cudaEventRecord(ev_fork, 0);
    cudaStreamWaitEvent(s2, ev_fork, 0);

    // -- stream 0: projection path --
    wsplit_kernel<<<(IN_F * HD + 255) / 256, 256>>>(W);
    mma_gemm_kernel<<<(N_NODES + 63) / 64, 512, GEMM_SMEM>>>(feat, al, ar);

    // -- stream s2: CSR build path --
    zero_kernel<<<(N_NODES + 255) / 256, 256, 0, s2>>>();
    hist_kernel<<<(N_EDGES / 4 + 255) / 256, 256, 0, s2>>>(dst);
    scan1_kernel<<<SCAN_BLOCKS, 1024, 0, s2>>>();
    scan2_kernel<<<1, 64, 0, s2>>>();
    scan3_kernel<<<SCAN_BLOCKS, 1024, 0, s2>>>();
    scatter_kernel<<<(N_EDGES / 4 + 255) / 256, 256, 0, s2>>>(src, dst);

    cudaEventRecord(ev_join, s2);
    cudaStreamWaitEvent(0, ev_join, 0);

    aggregate_kernel<<<1184, 256>>>(out);
}